// round 14
// baseline (speedup 1.0000x reference)
#include <cuda_runtime.h>
#include <cuda_fp16.h>
#include <cstdint>

// Problem dims
#define BB 64
#define RR 50
#define LL 15
#define DD 1024
#define FF 4096

// GEMM: M=B*R=3200, N=D=1024, K=F=4096
#define GM 3200
#define GN 1024
#define GK 4096

#define BM 128
#define BN 128
#define BK 64
#define NTILE 200                 // 25 x 8
#define NFULL 148                 // tiles 0..147: full-K, one exact wave
#define NTAIL (NTILE - NFULL)     // 52
#define TSPLIT 4
#define NTAILCTA (NTAIL * TSPLIT) // 208
#define NIT_FULL (GK / BK)        // 64
#define NIT_TAIL (GK / BK / TSPLIT) // 16

#define APH 72
#define STAGES 4
#define A_STAGE_BYTES (BM * APH * 2)          // 18432
#define STAGE_BYTES (2 * BM * APH * 2)        // 36864
#define SMEM_TOTAL (STAGES * STAGE_BYTES)     // 147456
#define NTHREADS 256

// pooling: full kernel covers rows 0..2515 (17/CTA); tail kernel covers 2516..3199 (4/CTA)
#define PROWS_F 17
#define POOL_SPLIT (NFULL * PROWS_F)   // 2516
#define PROWS_T 4
#define PGROUP 4

__device__ __half g_Ah[GM * GK];
__device__ __half g_Wh[GN * GK];
__device__ float g_scr[NTAILCTA * BM * BN];
__device__ float g_invlen[GM];

__device__ __forceinline__ void mma_f16(float& c0, float& c1, float& c2, float& c3,
                                        uint32_t a0, uint32_t a1, uint32_t a2, uint32_t a3,
                                        uint32_t b0, uint32_t b1) {
    asm volatile(
        "mma.sync.aligned.m16n8k16.row.col.f32.f16.f16.f32 "
        "{%0,%1,%2,%3}, {%4,%5,%6,%7}, {%8,%9}, {%0,%1,%2,%3};\n"
        : "+f"(c0), "+f"(c1), "+f"(c2), "+f"(c3)
        : "r"(a0), "r"(a1), "r"(a2), "r"(a3), "r"(b0), "r"(b1));
}

__device__ __forceinline__ uint32_t smem_u32(const void* p) {
    uint32_t a;
    asm("{ .reg .u64 t; cvta.to.shared.u64 t, %1; cvt.u32.u64 %0, t; }" : "=r"(a) : "l"(p));
    return a;
}

#define CP_ASYNC16(dst, src) \
    asm volatile("cp.async.cg.shared.global [%0], [%1], 16;" :: "r"(dst), "l"(src) : "memory")
#define CP_COMMIT() asm volatile("cp.async.commit_group;" ::: "memory")
#define CP_WAIT(n) asm volatile("cp.async.wait_group %0;" :: "n"(n) : "memory")

#define LDSM4(r0, r1, r2, r3, addr) \
    asm volatile("ldmatrix.sync.aligned.m8n8.x4.shared.b16 {%0,%1,%2,%3}, [%4];" \
                 : "=r"(r0), "=r"(r1), "=r"(r2), "=r"(r3) : "r"(addr))

// ─────────────────── prepass: fp32 -> fp16(rna), plus 1/len ───────────────────
__global__ void __launch_bounds__(256)
cvt_f16_kernel(const float* __restrict__ A, const float* __restrict__ W,
               const int* __restrict__ lens) {
    const int gid = blockIdx.x * blockDim.x + threadIdx.x;
    if (gid < GM) g_invlen[gid] = 1.0f / (float)__ldg(lens + gid);

    const int na8 = GM * GK / 8;
    const int nw8 = GN * GK / 8;
    const int total = na8 + nw8;
    for (int i = gid; i < total; i += gridDim.x * blockDim.x) {
        const float4* src;
        uint4* dst;
        if (i < na8) {
            src = (const float4*)A + (size_t)i * 2;
            dst = (uint4*)g_Ah + i;
        } else {
            src = (const float4*)W + (size_t)(i - na8) * 2;
            dst = (uint4*)g_Wh + (i - na8);
        }
        float4 v0 = __ldg(src);
        float4 v1 = __ldg(src + 1);
        __half2 h0 = __floats2half2_rn(v0.x, v0.y);
        __half2 h1 = __floats2half2_rn(v0.z, v0.w);
        __half2 h2 = __floats2half2_rn(v1.x, v1.y);
        __half2 h3 = __floats2half2_rn(v1.z, v1.w);
        uint4 o4;
        o4.x = *(uint32_t*)&h0;
        o4.y = *(uint32_t*)&h1;
        o4.z = *(uint32_t*)&h2;
        o4.w = *(uint32_t*)&h3;
        *dst = o4;
    }
}

// ───────── kernel 1: 148 full-K tiles (one wave), direct epilogue, fused pool ─────────
__global__ void __launch_bounds__(NTHREADS, 1)
gemm_full_kernel(const float* __restrict__ phrases, const float* __restrict__ bias,
                 float* __restrict__ out) {
    extern __shared__ char smem[];
    const uint32_t sb = smem_u32(smem);

    const int tid = threadIdx.x;
    const int warp = tid >> 5;
    const int lane = tid & 31;
    const int warp_m = warp & 1;
    const int warp_n = warp >> 1;
    const int m0 = (blockIdx.x >> 3) * BM;
    const int n0 = (blockIdx.x & 7) * BN;

    const int prow0 = blockIdx.x * PROWS_F;
    const int msteps = PROWS_F * LL;    // 255
    const float4* pf = (const float4*)(phrases + (size_t)prow0 * LL * DD) + tid;

    uint32_t a_dst[4], b_dst[4];
    const __half* a_src[4];
    const __half* b_src[4];
#pragma unroll
    for (int i = 0; i < 4; i++) {
        int id = tid + i * NTHREADS;
        int row = id >> 3, c8 = id & 7;
        a_dst[i] = row * (APH * 2) + c8 * 16;
        b_dst[i] = A_STAGE_BYTES + row * (APH * 2) + c8 * 16;
        a_src[i] = g_Ah + (size_t)(m0 + row) * GK + c8 * 8;
        b_src[i] = g_Wh + (size_t)(n0 + row) * GK + c8 * 8;
    }

    const int la_row = (lane & 7) + ((lane >> 3) & 1) * 8;
    const uint32_t pA_base = ((warp_m * 64 + la_row) * APH + (lane >> 4) * 8) * 2;
    const int lb_row = (lane & 7) + ((lane >> 4) & 1) * 8;
    const uint32_t pB_base =
        A_STAGE_BYTES + ((warp_n * 32 + lb_row) * APH + ((lane >> 3) & 1) * 8) * 2;

    float acc[4][4][4];
#pragma unroll
    for (int tm = 0; tm < 4; tm++)
#pragma unroll
        for (int tn = 0; tn < 4; tn++)
#pragma unroll
            for (int r = 0; r < 4; r++) acc[tm][tn][r] = 0.0f;

#pragma unroll
    for (int s = 0; s < STAGES - 1; s++) {
        const uint32_t st = sb + s * STAGE_BYTES;
        const int k0 = s * BK;
#pragma unroll
        for (int i = 0; i < 4; i++) {
            CP_ASYNC16(st + a_dst[i], a_src[i] + k0);
            CP_ASYNC16(st + b_dst[i], b_src[i] + k0);
        }
        CP_COMMIT();
    }

    float4 pbuf[PGROUP];
#pragma unroll
    for (int j = 0; j < PGROUP; j++) pbuf[j] = __ldg(pf + j * (DD / 4));
    float pacc0 = 0.f, pacc1 = 0.f, pacc2 = 0.f, pacc3 = 0.f;
    float pinv = 0.f;
    int parow = 0, ppl = 0;

    uint32_t af[2][4][4], bf[2][4][2];

    for (int it = 0; it < NIT_FULL; it++) {
        CP_WAIT(STAGES - 2);
        __syncthreads();

        {
            const int ld = it + STAGES - 1;
            if (ld < NIT_FULL) {
                const uint32_t st = sb + (ld & (STAGES - 1)) * STAGE_BYTES;
                const int k0 = ld * BK;
#pragma unroll
                for (int i = 0; i < 4; i++) {
                    CP_ASYNC16(st + a_dst[i], a_src[i] + k0);
                    CP_ASYNC16(st + b_dst[i], b_src[i] + k0);
                }
            }
            CP_COMMIT();
        }

        if (it * PGROUP < msteps) {
#pragma unroll
            for (int j = 0; j < PGROUP; j++) {
                if (it * PGROUP + j < msteps) {
                    if (ppl == 0) pinv = __ldg(g_invlen + prow0 + parow);
                    pacc0 += pbuf[j].x; pacc1 += pbuf[j].y;
                    pacc2 += pbuf[j].z; pacc3 += pbuf[j].w;
                    ppl++;
                    if (ppl == LL) {
                        float4 r = make_float4(pacc0 * pinv, pacc1 * pinv,
                                               pacc2 * pinv, pacc3 * pinv);
                        *((float4*)(out + (size_t)(prow0 + parow) * (2 * GN) + GN) + tid) = r;
                        pacc0 = pacc1 = pacc2 = pacc3 = 0.f;
                        ppl = 0;
                        parow++;
                    }
                }
            }
            const int sbase = (it + 1) * PGROUP;
#pragma unroll
            for (int j = 0; j < PGROUP; j++)
                if (sbase + j < msteps) pbuf[j] = __ldg(pf + (sbase + j) * (DD / 4));
        }

        const uint32_t st = sb + (it & (STAGES - 1)) * STAGE_BYTES;
        const uint32_t aA = st + pA_base;
        const uint32_t aB = st + pB_base;

#pragma unroll
        for (int tm = 0; tm < 4; tm++)
            LDSM4(af[0][tm][0], af[0][tm][1], af[0][tm][2], af[0][tm][3],
                  aA + (tm * 16 * APH) * 2);
#pragma unroll
        for (int pr = 0; pr < 2; pr++)
            LDSM4(bf[0][pr * 2][0], bf[0][pr * 2][1], bf[0][pr * 2 + 1][0], bf[0][pr * 2 + 1][1],
                  aB + (pr * 16 * APH) * 2);

#pragma unroll
        for (int ks = 0; ks < 4; ks++) {
            const int cur = ks & 1, nxt = cur ^ 1;
            if (ks < 3) {
                const uint32_t ko = (ks + 1) * 32;
#pragma unroll
                for (int tm = 0; tm < 4; tm++)
                    LDSM4(af[nxt][tm][0], af[nxt][tm][1], af[nxt][tm][2], af[nxt][tm][3],
                          aA + (tm * 16 * APH) * 2 + ko);
#pragma unroll
                for (int pr = 0; pr < 2; pr++)
                    LDSM4(bf[nxt][pr * 2][0], bf[nxt][pr * 2][1],
                          bf[nxt][pr * 2 + 1][0], bf[nxt][pr * 2 + 1][1],
                          aB + (pr * 16 * APH) * 2 + ko);
            }
#pragma unroll
            for (int tm = 0; tm < 4; tm++)
#pragma unroll
                for (int tn = 0; tn < 4; tn++)
                    mma_f16(acc[tm][tn][0], acc[tm][tn][1], acc[tm][tn][2], acc[tm][tn][3],
                            af[cur][tm][0], af[cur][tm][1], af[cur][tm][2], af[cur][tm][3],
                            bf[cur][tn][0], bf[cur][tn][1]);
        }
    }

    // direct epilogue: relu(acc + bias) -> out[:, 0:1024]
#pragma unroll
    for (int tn = 0; tn < 4; tn++) {
        const int n = n0 + warp_n * 32 + tn * 8 + (lane & 3) * 2;
        const float b0 = __ldg(bias + n);
        const float b1 = __ldg(bias + n + 1);
#pragma unroll
        for (int tm = 0; tm < 4; tm++) {
            const int r0 = m0 + warp_m * 64 + tm * 16 + (lane >> 2);
            float2 v0, v1;
            v0.x = fmaxf(acc[tm][tn][0] + b0, 0.0f);
            v0.y = fmaxf(acc[tm][tn][1] + b1, 0.0f);
            v1.x = fmaxf(acc[tm][tn][2] + b0, 0.0f);
            v1.y = fmaxf(acc[tm][tn][3] + b1, 0.0f);
            *(float2*)(out + (size_t)r0 * (2 * GN) + n) = v0;
            *(float2*)(out + (size_t)(r0 + 8) * (2 * GN) + n) = v1;
        }
    }
}

// ───────── kernel 2: 52 tail tiles x split-4, partials to scratch, pool remainder ─────────
__global__ void __launch_bounds__(NTHREADS, 1)
gemm_tail_kernel(const float* __restrict__ phrases, float* __restrict__ out) {
    extern __shared__ char smem[];
    const uint32_t sb = smem_u32(smem);

    const int tid = threadIdx.x;
    const int warp = tid >> 5;
    const int lane = tid & 31;
    const int warp_m = warp & 1;
    const int warp_n = warp >> 1;

    const int tb = blockIdx.x;              // 0..207
    const int t = NFULL + (tb >> 2);        // tile 148..199
    const int m0 = (t >> 3) * BM;
    const int n0 = (t & 7) * BN;
    const int kbase = (tb & 3) * (GK / TSPLIT);
    float* scr = g_scr + (size_t)tb * (BM * BN);

    const int prow0 = POOL_SPLIT + tb * PROWS_T;
    const int vrows = max(0, min(PROWS_T, GM - prow0));
    const int msteps = vrows * LL;          // 0 or 60
    const float4* pf = (const float4*)(phrases + (size_t)prow0 * LL * DD) + tid;

    uint32_t a_dst[4], b_dst[4];
    const __half* a_src[4];
    const __half* b_src[4];
#pragma unroll
    for (int i = 0; i < 4; i++) {
        int id = tid + i * NTHREADS;
        int row = id >> 3, c8 = id & 7;
        a_dst[i] = row * (APH * 2) + c8 * 16;
        b_dst[i] = A_STAGE_BYTES + row * (APH * 2) + c8 * 16;
        a_src[i] = g_Ah + (size_t)(m0 + row) * GK + kbase + c8 * 8;
        b_src[i] = g_Wh + (size_t)(n0 + row) * GK + kbase + c8 * 8;
    }

    const int la_row = (lane & 7) + ((lane >> 3) & 1) * 8;
    const uint32_t pA_base = ((warp_m * 64 + la_row) * APH + (lane >> 4) * 8) * 2;
    const int lb_row = (lane & 7) + ((lane >> 4) & 1) * 8;
    const uint32_t pB_base =
        A_STAGE_BYTES + ((warp_n * 32 + lb_row) * APH + ((lane >> 3) & 1) * 8) * 2;

    float acc[4][4][4];
#pragma unroll
    for (int tm = 0; tm < 4; tm++)
#pragma unroll
        for (int tn = 0; tn < 4; tn++)
#pragma unroll
            for (int r = 0; r < 4; r++) acc[tm][tn][r] = 0.0f;

#pragma unroll
    for (int s = 0; s < STAGES - 1; s++) {
        const uint32_t st = sb + s * STAGE_BYTES;
        const int k0 = s * BK;
#pragma unroll
        for (int i = 0; i < 4; i++) {
            CP_ASYNC16(st + a_dst[i], a_src[i] + k0);
            CP_ASYNC16(st + b_dst[i], b_src[i] + k0);
        }
        CP_COMMIT();
    }

    float4 pbuf[PGROUP];
#pragma unroll
    for (int j = 0; j < PGROUP; j++)
        pbuf[j] = (j < msteps) ? __ldg(pf + j * (DD / 4)) : make_float4(0.f, 0.f, 0.f, 0.f);
    float pacc0 = 0.f, pacc1 = 0.f, pacc2 = 0.f, pacc3 = 0.f;
    float pinv = 0.f;
    int parow = 0, ppl = 0;

    uint32_t af[2][4][4], bf[2][4][2];

    for (int it = 0; it < NIT_TAIL; it++) {
        CP_WAIT(STAGES - 2);
        __syncthreads();

        {
            const int ld = it + STAGES - 1;
            if (ld < NIT_TAIL) {
                const uint32_t st = sb + (ld & (STAGES - 1)) * STAGE_BYTES;
                const int k0 = ld * BK;
#pragma unroll
                for (int i = 0; i < 4; i++) {
                    CP_ASYNC16(st + a_dst[i], a_src[i] + k0);
                    CP_ASYNC16(st + b_dst[i], b_src[i] + k0);
                }
            }
            CP_COMMIT();
        }

        if (it * PGROUP < msteps) {
#pragma unroll
            for (int j = 0; j < PGROUP; j++) {
                if (it * PGROUP + j < msteps) {
                    if (ppl == 0) pinv = __ldg(g_invlen + prow0 + parow);
                    pacc0 += pbuf[j].x; pacc1 += pbuf[j].y;
                    pacc2 += pbuf[j].z; pacc3 += pbuf[j].w;
                    ppl++;
                    if (ppl == LL) {
                        float4 r = make_float4(pacc0 * pinv, pacc1 * pinv,
                                               pacc2 * pinv, pacc3 * pinv);
                        *((float4*)(out + (size_t)(prow0 + parow) * (2 * GN) + GN) + tid) = r;
                        pacc0 = pacc1 = pacc2 = pacc3 = 0.f;
                        ppl = 0;
                        parow++;
                    }
                }
            }
            const int sbase = (it + 1) * PGROUP;
#pragma unroll
            for (int j = 0; j < PGROUP; j++)
                if (sbase + j < msteps) pbuf[j] = __ldg(pf + (sbase + j) * (DD / 4));
        }

        const uint32_t st = sb + (it & (STAGES - 1)) * STAGE_BYTES;
        const uint32_t aA = st + pA_base;
        const uint32_t aB = st + pB_base;

#pragma unroll
        for (int tm = 0; tm < 4; tm++)
            LDSM4(af[0][tm][0], af[0][tm][1], af[0][tm][2], af[0][tm][3],
                  aA + (tm * 16 * APH) * 2);
#pragma unroll
        for (int pr = 0; pr < 2; pr++)
            LDSM4(bf[0][pr * 2][0], bf[0][pr * 2][1], bf[0][pr * 2 + 1][0], bf[0][pr * 2 + 1][1],
                  aB + (pr * 16 * APH) * 2);

#pragma unroll
        for (int ks = 0; ks < 4; ks++) {
            const int cur = ks & 1, nxt = cur ^ 1;
            if (ks < 3) {
                const uint32_t ko = (ks + 1) * 32;
#pragma unroll
                for (int tm = 0; tm < 4; tm++)
                    LDSM4(af[nxt][tm][0], af[nxt][tm][1], af[nxt][tm][2], af[nxt][tm][3],
                          aA + (tm * 16 * APH) * 2 + ko);
#pragma unroll
                for (int pr = 0; pr < 2; pr++)
                    LDSM4(bf[nxt][pr * 2][0], bf[nxt][pr * 2][1],
                          bf[nxt][pr * 2 + 1][0], bf[nxt][pr * 2 + 1][1],
                          aB + (pr * 16 * APH) * 2 + ko);
            }
#pragma unroll
            for (int tm = 0; tm < 4; tm++)
#pragma unroll
                for (int tn = 0; tn < 4; tn++)
                    mma_f16(acc[tm][tn][0], acc[tm][tn][1], acc[tm][tn][2], acc[tm][tn][3],
                            af[cur][tm][0], af[cur][tm][1], af[cur][tm][2], af[cur][tm][3],
                            bf[cur][tn][0], bf[cur][tn][1]);
        }
    }

    // raw partial to scratch
#pragma unroll
    for (int tn = 0; tn < 4; tn++) {
        const int n = warp_n * 32 + tn * 8 + (lane & 3) * 2;
#pragma unroll
        for (int tm = 0; tm < 4; tm++) {
            const int r0 = warp_m * 64 + tm * 16 + (lane >> 2);
            *(float2*)(scr + r0 * BN + n) = make_float2(acc[tm][tn][0], acc[tm][tn][1]);
            *(float2*)(scr + (r0 + 8) * BN + n) = make_float2(acc[tm][tn][2], acc[tm][tn][3]);
        }
    }
}

// ───── reduce (tail tiles only): sum 4 partials (ascending k) + bias + relu ─────
__global__ void __launch_bounds__(256)
reduce_tail_kernel(const float* __restrict__ bias, float* __restrict__ out) {
    const int r = blockIdx.x;               // 0..51
    const int t = NFULL + r;
    const int m0 = (t >> 3) * BM;
    const int n0 = (t & 7) * BN;
    const int tid = threadIdx.x;
    const float* s0 = g_scr + (size_t)(r * 4 + 0) * (BM * BN);
    const float* s1 = g_scr + (size_t)(r * 4 + 1) * (BM * BN);
    const float* s2 = g_scr + (size_t)(r * 4 + 2) * (BM * BN);
    const float* s3 = g_scr + (size_t)(r * 4 + 3) * (BM * BN);

#pragma unroll
    for (int i = 0; i < 16; i++) {
        const int idx = tid + i * 256;
        const int row = idx >> 5, c4 = idx & 31;
        const int o = row * BN + c4 * 4;
        float4 p = *(const float4*)(s0 + o);
        float4 q1 = *(const float4*)(s1 + o);
        float4 q2 = *(const float4*)(s2 + o);
        float4 q3 = *(const float4*)(s3 + o);
        p.x = ((p.x + q1.x) + q2.x) + q3.x;
        p.y = ((p.y + q1.y) + q2.y) + q3.y;
        p.z = ((p.z + q1.z) + q2.z) + q3.z;
        p.w = ((p.w + q1.w) + q2.w) + q3.w;
        float4 bv = __ldg((const float4*)(bias + n0) + c4);
        float4 v;
        v.x = fmaxf(p.x + bv.x, 0.0f);
        v.y = fmaxf(p.y + bv.y, 0.0f);
        v.z = fmaxf(p.z + bv.z, 0.0f);
        v.w = fmaxf(p.w + bv.w, 0.0f);
        *(float4*)(out + (size_t)(m0 + row) * (2 * GN) + n0 + c4 * 4) = v;
    }
}

extern "C" void kernel_launch(void* const* d_in, const int* in_sizes, int n_in,
                              void* d_out, int out_size) {
    const float* features = (const float*)d_in[0];
    const float* phrases  = (const float*)d_in[1];
    const float* W        = (const float*)d_in[2];
    const float* bias     = (const float*)d_in[3];
    const int*   lens     = (const int*)d_in[4];
    float* out = (float*)d_out;

    cvt_f16_kernel<<<2048, 256>>>(features, W, lens);

    cudaFuncSetAttribute(gemm_full_kernel, cudaFuncAttributeMaxDynamicSharedMemorySize,
                         SMEM_TOTAL);
    cudaFuncSetAttribute(gemm_tail_kernel, cudaFuncAttributeMaxDynamicSharedMemorySize,
                         SMEM_TOTAL);

    gemm_full_kernel<<<NFULL, NTHREADS, SMEM_TOTAL>>>(phrases, bias, out);
    gemm_tail_kernel<<<NTAILCTA, NTHREADS, SMEM_TOTAL>>>(phrases, out);
    reduce_tail_kernel<<<NTAIL, 256>>>(bias, out);
}

// round 15
// speedup vs baseline: 1.6882x; 1.6882x over previous
#include <cuda_runtime.h>
#include <cuda_fp16.h>
#include <cstdint>

// Problem dims
#define BB 64
#define RR 50
#define LL 15
#define DD 1024
#define FF 4096

// GEMM: M=B*R=3200, N=D=1024, K=F=4096
#define GM 3200
#define GN 1024
#define GK 4096

// CTA tile 128x128x64 (fp16), split-K=2 -> grid (8, 25, 2) = 400 CTAs.
#define BM 128
#define BN 128
#define BK 64
#define KSPLIT 2
#define KHALF (GK / KSPLIT)         // 2048
#define NIT (KHALF / BK)            // 32
#define APH 72                      // padded row stride in halves (144B, conflict-free)
#define STAGES 4
#define A_STAGE_BYTES (BM * APH * 2)          // 18432
#define STAGE_BYTES (2 * BM * APH * 2)        // 36864 (A + B)
#define SMEM_TOTAL (STAGES * STAGE_BYTES)     // 147456
#define NTHREADS 256

// pooling fused into GEMM: 400 CTAs x 8 rows, 120 row-steps, 4 per iteration
#define PROWS 8
#define PSTEPS (PROWS * LL)          // 120
#define PGROUP 4

// fp16(rna) copies of A and W; split-1 partial scratch; 1/len
__device__ __half g_Ah[GM * GK];
__device__ __half g_Wh[GN * GK];
__device__ float g_part[GM * GN];
__device__ float g_invlen[GM];

// f16-accumulate mma: d(2xf16x2) = a*b + d
__device__ __forceinline__ void mma_f16h_acc(uint32_t& d0, uint32_t& d1,
                                             uint32_t a0, uint32_t a1, uint32_t a2, uint32_t a3,
                                             uint32_t b0, uint32_t b1) {
    asm volatile(
        "mma.sync.aligned.m16n8k16.row.col.f16.f16.f16.f16 "
        "{%0,%1}, {%2,%3,%4,%5}, {%6,%7}, {%0,%1};\n"
        : "+r"(d0), "+r"(d1)
        : "r"(a0), "r"(a1), "r"(a2), "r"(a3), "r"(b0), "r"(b1));
}

// f16-accumulate mma, fresh window: d = a*b + 0
__device__ __forceinline__ void mma_f16h_zero(uint32_t& d0, uint32_t& d1,
                                              uint32_t a0, uint32_t a1, uint32_t a2, uint32_t a3,
                                              uint32_t b0, uint32_t b1) {
    asm volatile(
        "{ .reg .b32 z; mov.b32 z, 0;\n"
        "mma.sync.aligned.m16n8k16.row.col.f16.f16.f16.f16 "
        "{%0,%1}, {%2,%3,%4,%5}, {%6,%7}, {z,z}; }\n"
        : "=r"(d0), "=r"(d1)
        : "r"(a0), "r"(a1), "r"(a2), "r"(a3), "r"(b0), "r"(b1));
}

__device__ __forceinline__ uint32_t smem_u32(const void* p) {
    uint32_t a;
    asm("{ .reg .u64 t; cvta.to.shared.u64 t, %1; cvt.u32.u64 %0, t; }" : "=r"(a) : "l"(p));
    return a;
}

#define CP_ASYNC16(dst, src) \
    asm volatile("cp.async.cg.shared.global [%0], [%1], 16;" :: "r"(dst), "l"(src) : "memory")
#define CP_COMMIT() asm volatile("cp.async.commit_group;" ::: "memory")
#define CP_WAIT(n) asm volatile("cp.async.wait_group %0;" :: "n"(n) : "memory")

#define LDSM4(r0, r1, r2, r3, addr) \
    asm volatile("ldmatrix.sync.aligned.m8n8.x4.shared.b16 {%0,%1,%2,%3}, [%4];" \
                 : "=r"(r0), "=r"(r1), "=r"(r2), "=r"(r3) : "r"(addr))

// ─────────────────── prepass: fp32 -> fp16(rna), plus 1/len ───────────────────
__global__ void __launch_bounds__(256)
cvt_f16_kernel(const float* __restrict__ A, const float* __restrict__ W,
               const int* __restrict__ lens) {
    const int gid = blockIdx.x * blockDim.x + threadIdx.x;
    if (gid < GM) g_invlen[gid] = 1.0f / (float)__ldg(lens + gid);

    const int na8 = GM * GK / 8;   // 16B output chunks for A
    const int nw8 = GN * GK / 8;
    const int total = na8 + nw8;
    for (int i = gid; i < total; i += gridDim.x * blockDim.x) {
        const float4* src;
        uint4* dst;
        if (i < na8) {
            src = (const float4*)A + (size_t)i * 2;
            dst = (uint4*)g_Ah + i;
        } else {
            src = (const float4*)W + (size_t)(i - na8) * 2;
            dst = (uint4*)g_Wh + (i - na8);
        }
        float4 v0 = __ldg(src);
        float4 v1 = __ldg(src + 1);
        __half2 h0 = __floats2half2_rn(v0.x, v0.y);
        __half2 h1 = __floats2half2_rn(v0.z, v0.w);
        __half2 h2 = __floats2half2_rn(v1.x, v1.y);
        __half2 h3 = __floats2half2_rn(v1.z, v1.w);
        uint4 o4;
        o4.x = *(uint32_t*)&h0;
        o4.y = *(uint32_t*)&h1;
        o4.z = *(uint32_t*)&h2;
        o4.w = *(uint32_t*)&h3;
        *dst = o4;
    }
}

// ── GEMM partials (fp16 in, f16 window acc + f32 master), split-K=2, fused pool ──
__global__ void __launch_bounds__(NTHREADS, 1)
gemm_partial_kernel(const float* __restrict__ phrases, float* __restrict__ out) {
    extern __shared__ char smem[];
    const uint32_t sb = smem_u32(smem);

    const int tid = threadIdx.x;
    const int warp = tid >> 5;      // 0..7
    const int lane = tid & 31;
    const int warp_m = warp & 1;    // 0..1 -> 64-row slab
    const int warp_n = warp >> 1;   // 0..3 -> 32-col slab
    const int m0 = blockIdx.y * BM;
    const int n0 = blockIdx.x * BN;
    const int kbase = blockIdx.z * KHALF;

    // pooling assignment: CTA linear id -> 8 phrase rows
    const int cid = blockIdx.z * (GN / BN) * (GM / BM) + blockIdx.y * (GN / BN) + blockIdx.x;
    const int prow0 = cid * PROWS;
    const float4* pf = (const float4*)(phrases + (size_t)prow0 * LL * DD) + tid;

    // cp.async mappings: tile = 128 rows x 8 16B-chunks (64 halves); 4 chunks/thread each
    uint32_t a_dst[4], b_dst[4];
    const __half* a_src[4];
    const __half* b_src[4];
#pragma unroll
    for (int i = 0; i < 4; i++) {
        int id = tid + i * NTHREADS;     // 0..1023
        int row = id >> 3, c8 = id & 7;
        a_dst[i] = row * (APH * 2) + c8 * 16;
        b_dst[i] = A_STAGE_BYTES + row * (APH * 2) + c8 * 16;
        a_src[i] = g_Ah + (size_t)(m0 + row) * GK + kbase + c8 * 8;
        b_src[i] = g_Wh + (size_t)(n0 + row) * GK + kbase + c8 * 8;
    }

    // ldmatrix lane bases (byte offsets within a stage)
    const int la_row = (lane & 7) + ((lane >> 3) & 1) * 8;
    const uint32_t pA_base = ((warp_m * 64 + la_row) * APH + (lane >> 4) * 8) * 2;
    const int lb_row = (lane & 7) + ((lane >> 4) & 1) * 8;
    const uint32_t pB_base =
        A_STAGE_BYTES + ((warp_n * 32 + lb_row) * APH + ((lane >> 3) & 1) * 8) * 2;

    float acc[4][4][4];
#pragma unroll
    for (int tm = 0; tm < 4; tm++)
#pragma unroll
        for (int tn = 0; tn < 4; tn++)
#pragma unroll
            for (int r = 0; r < 4; r++) acc[tm][tn][r] = 0.0f;

    // preload stages 0..STAGES-2
#pragma unroll
    for (int s = 0; s < STAGES - 1; s++) {
        const uint32_t st = sb + s * STAGE_BYTES;
        const int k0 = s * BK;
#pragma unroll
        for (int i = 0; i < 4; i++) {
            CP_ASYNC16(st + a_dst[i], a_src[i] + k0);
            CP_ASYNC16(st + b_dst[i], b_src[i] + k0);
        }
        CP_COMMIT();
    }

    // pool state: prefetch group 0 (steps 0..3)
    float4 pbuf[PGROUP];
#pragma unroll
    for (int j = 0; j < PGROUP; j++) pbuf[j] = __ldg(pf + j * (DD / 4));
    float pacc0 = 0.f, pacc1 = 0.f, pacc2 = 0.f, pacc3 = 0.f;
    float pinv = 0.f;
    int parow = 0, ppl = 0;

    uint32_t af[4][4], bf[4][2];       // single-buffered fragments
    uint32_t ch[4][4][2];              // f16x2 window accumulators

    for (int it = 0; it < NIT; it++) {
        CP_WAIT(STAGES - 2);
        __syncthreads();

        // issue loads for stage it+STAGES-1
        {
            const int ld = it + STAGES - 1;
            if (ld < NIT) {
                const uint32_t st = sb + (ld & (STAGES - 1)) * STAGE_BYTES;
                const int k0 = ld * BK;
#pragma unroll
                for (int i = 0; i < 4; i++) {
                    CP_ASYNC16(st + a_dst[i], a_src[i] + k0);
                    CP_ASYNC16(st + b_dst[i], b_src[i] + k0);
                }
            }
            CP_COMMIT();
        }

        // ── fused pooling: accumulate group `it` (already in pbuf), then prefetch it+1 ──
        if (it * PGROUP < PSTEPS) {
#pragma unroll
            for (int j = 0; j < PGROUP; j++) {
                if (ppl == 0) pinv = __ldg(g_invlen + prow0 + parow);
                pacc0 += pbuf[j].x; pacc1 += pbuf[j].y;
                pacc2 += pbuf[j].z; pacc3 += pbuf[j].w;
                ppl++;
                if (ppl == LL) {
                    float4 r = make_float4(pacc0 * pinv, pacc1 * pinv, pacc2 * pinv, pacc3 * pinv);
                    *((float4*)(out + (size_t)(prow0 + parow) * (2 * GN) + GN) + tid) = r;
                    pacc0 = pacc1 = pacc2 = pacc3 = 0.f;
                    ppl = 0;
                    parow++;
                }
            }
            const int sbase = (it + 1) * PGROUP;
            if (sbase < PSTEPS) {
#pragma unroll
                for (int j = 0; j < PGROUP; j++)
                    pbuf[j] = __ldg(pf + (sbase + j) * (DD / 4));
            }
        }

        const uint32_t st = sb + (it & (STAGES - 1)) * STAGE_BYTES;
        const uint32_t aA = st + pA_base;
        const uint32_t aB = st + pB_base;

        // 4 k16-steps chained in f16 window accumulators
#pragma unroll
        for (int ks = 0; ks < 4; ks++) {
            const uint32_t ko = ks * 32;   // 16 halves = 32 bytes
#pragma unroll
            for (int tm = 0; tm < 4; tm++)
                LDSM4(af[tm][0], af[tm][1], af[tm][2], af[tm][3],
                      aA + (tm * 16 * APH) * 2 + ko);
#pragma unroll
            for (int pr = 0; pr < 2; pr++)
                LDSM4(bf[pr * 2][0], bf[pr * 2][1], bf[pr * 2 + 1][0], bf[pr * 2 + 1][1],
                      aB + (pr * 16 * APH) * 2 + ko);
            if (ks == 0) {
#pragma unroll
                for (int tm = 0; tm < 4; tm++)
#pragma unroll
                    for (int tn = 0; tn < 4; tn++)
                        mma_f16h_zero(ch[tm][tn][0], ch[tm][tn][1],
                                      af[tm][0], af[tm][1], af[tm][2], af[tm][3],
                                      bf[tn][0], bf[tn][1]);
            } else {
#pragma unroll
                for (int tm = 0; tm < 4; tm++)
#pragma unroll
                    for (int tn = 0; tn < 4; tn++)
                        mma_f16h_acc(ch[tm][tn][0], ch[tm][tn][1],
                                     af[tm][0], af[tm][1], af[tm][2], af[tm][3],
                                     bf[tn][0], bf[tn][1]);
            }
        }

        // fold window into f32 master accumulators
#pragma unroll
        for (int tm = 0; tm < 4; tm++)
#pragma unroll
            for (int tn = 0; tn < 4; tn++) {
                float2 lo = __half22float2(*(__half2*)&ch[tm][tn][0]);
                float2 hi = __half22float2(*(__half2*)&ch[tm][tn][1]);
                acc[tm][tn][0] += lo.x;
                acc[tm][tn][1] += lo.y;
                acc[tm][tn][2] += hi.x;
                acc[tm][tn][3] += hi.y;
            }
    }

    // write raw partial: split 0 -> out[:, 0:1024] (stride 2048); split 1 -> g_part
    float* dst = (blockIdx.z == 0) ? out : g_part;
    const int stride = (blockIdx.z == 0) ? (2 * GN) : GN;
#pragma unroll
    for (int tn = 0; tn < 4; tn++) {
        const int n = n0 + warp_n * 32 + tn * 8 + (lane & 3) * 2;
#pragma unroll
        for (int tm = 0; tm < 4; tm++) {
            const int r0 = m0 + warp_m * 64 + tm * 16 + (lane >> 2);
            *(float2*)(dst + (size_t)r0 * stride + n) = make_float2(acc[tm][tn][0], acc[tm][tn][1]);
            *(float2*)(dst + (size_t)(r0 + 8) * stride + n) = make_float2(acc[tm][tn][2], acc[tm][tn][3]);
        }
    }
}

// ─────────────── reduce: out[:,0:1024] = relu(p0 + p1 + bias) ───────────────
__global__ void __launch_bounds__(256)
reduce_kernel(const float* __restrict__ bias, float* __restrict__ out) {
    const int row = blockIdx.x;
    const int t = threadIdx.x;                 // 0..255 -> float4 within 1024 cols
    float4* o = (float4*)(out + (size_t)row * (2 * GN)) + t;
    float4 p0 = *o;
    float4 p1 = __ldg((const float4*)(g_part + (size_t)row * GN) + t);
    float4 bv = __ldg((const float4*)bias + t);
    float4 v;
    v.x = fmaxf(p0.x + p1.x + bv.x, 0.0f);
    v.y = fmaxf(p0.y + p1.y + bv.y, 0.0f);
    v.z = fmaxf(p0.z + p1.z + bv.z, 0.0f);
    v.w = fmaxf(p0.w + p1.w + bv.w, 0.0f);
    *o = v;
}

extern "C" void kernel_launch(void* const* d_in, const int* in_sizes, int n_in,
                              void* d_out, int out_size) {
    const float* features = (const float*)d_in[0];
    const float* phrases  = (const float*)d_in[1];
    const float* W        = (const float*)d_in[2];
    const float* bias     = (const float*)d_in[3];
    const int*   lens     = (const int*)d_in[4];
    float* out = (float*)d_out;

    cvt_f16_kernel<<<2048, 256>>>(features, W, lens);

    cudaFuncSetAttribute(gemm_partial_kernel, cudaFuncAttributeMaxDynamicSharedMemorySize,
                         SMEM_TOTAL);
    dim3 ggrid(GN / BN, GM / BM, KSPLIT);  // (8, 25, 2) = 400 CTAs
    gemm_partial_kernel<<<ggrid, NTHREADS, SMEM_TOTAL>>>(phrases, out);

    reduce_kernel<<<GM, 256>>>(bias, out);
}

// round 16
// speedup vs baseline: 1.7396x; 1.0305x over previous
#include <cuda_runtime.h>
#include <cuda_fp16.h>
#include <cstdint>

// Problem dims
#define BB 64
#define RR 50
#define LL 15
#define DD 1024
#define FF 4096

// GEMM: M=B*R=3200, N=D=1024, K=F=4096
#define GM 3200
#define GN 1024
#define GK 4096

// CTA tile 128x128x64 (fp16), split-K=2 -> grid (8, 25, 2) = 400 CTAs.
#define BM 128
#define BN 128
#define BK 64
#define KSPLIT 2
#define KHALF (GK / KSPLIT)         // 2048
#define NIT (KHALF / BK)            // 32
#define APH 72                      // padded row stride in halves (144B, conflict-free)
#define STAGES 4
#define A_STAGE_BYTES (BM * APH * 2)          // 18432
#define STAGE_BYTES (2 * BM * APH * 2)        // 36864 (A + B)
#define SMEM_TOTAL (STAGES * STAGE_BYTES)     // 147456
#define NTHREADS 256

// pooling fused into GEMM: 400 CTAs x 8 rows, 120 row-steps, 4 per iteration
#define PROWS 8
#define PSTEPS (PROWS * LL)          // 120
#define PGROUP 4

// fp16(rna) copies of A and W; split-0 partial scratch; 1/len; per-tile flags
__device__ __half g_Ah[GM * GK];
__device__ __half g_Wh[GN * GK];
__device__ float g_part[GM * GN];
__device__ float g_invlen[GM];
__device__ int g_flag[256];          // zero-init; z=1 consumer resets -> replay-safe

__device__ __forceinline__ void mma_f16(float& c0, float& c1, float& c2, float& c3,
                                        uint32_t a0, uint32_t a1, uint32_t a2, uint32_t a3,
                                        uint32_t b0, uint32_t b1) {
    asm volatile(
        "mma.sync.aligned.m16n8k16.row.col.f32.f16.f16.f32 "
        "{%0,%1,%2,%3}, {%4,%5,%6,%7}, {%8,%9}, {%0,%1,%2,%3};\n"
        : "+f"(c0), "+f"(c1), "+f"(c2), "+f"(c3)
        : "r"(a0), "r"(a1), "r"(a2), "r"(a3), "r"(b0), "r"(b1));
}

__device__ __forceinline__ uint32_t smem_u32(const void* p) {
    uint32_t a;
    asm("{ .reg .u64 t; cvta.to.shared.u64 t, %1; cvt.u32.u64 %0, t; }" : "=r"(a) : "l"(p));
    return a;
}

#define CP_ASYNC16(dst, src) \
    asm volatile("cp.async.cg.shared.global [%0], [%1], 16;" :: "r"(dst), "l"(src) : "memory")
#define CP_COMMIT() asm volatile("cp.async.commit_group;" ::: "memory")
#define CP_WAIT(n) asm volatile("cp.async.wait_group %0;" :: "n"(n) : "memory")

#define LDSM4(r0, r1, r2, r3, addr) \
    asm volatile("ldmatrix.sync.aligned.m8n8.x4.shared.b16 {%0,%1,%2,%3}, [%4];" \
                 : "=r"(r0), "=r"(r1), "=r"(r2), "=r"(r3) : "r"(addr))

// ─────────────────── prepass: fp32 -> fp16(rna), plus 1/len ───────────────────
__global__ void __launch_bounds__(256)
cvt_f16_kernel(const float* __restrict__ A, const float* __restrict__ W,
               const int* __restrict__ lens) {
    const int gid = blockIdx.x * blockDim.x + threadIdx.x;
    if (gid < GM) g_invlen[gid] = 1.0f / (float)__ldg(lens + gid);

    const int na8 = GM * GK / 8;   // 16B output chunks for A
    const int nw8 = GN * GK / 8;
    const int total = na8 + nw8;
    for (int i = gid; i < total; i += gridDim.x * blockDim.x) {
        const float4* src;
        uint4* dst;
        if (i < na8) {
            src = (const float4*)A + (size_t)i * 2;
            dst = (uint4*)g_Ah + i;
        } else {
            src = (const float4*)W + (size_t)(i - na8) * 2;
            dst = (uint4*)g_Wh + (i - na8);
        }
        float4 v0 = __ldg(src);
        float4 v1 = __ldg(src + 1);
        __half2 h0 = __floats2half2_rn(v0.x, v0.y);
        __half2 h1 = __floats2half2_rn(v0.z, v0.w);
        __half2 h2 = __floats2half2_rn(v1.x, v1.y);
        __half2 h3 = __floats2half2_rn(v1.z, v1.w);
        uint4 o4;
        o4.x = *(uint32_t*)&h0;
        o4.y = *(uint32_t*)&h1;
        o4.z = *(uint32_t*)&h2;
        o4.w = *(uint32_t*)&h3;
        *dst = o4;
    }
}

// ── GEMM (fp16 in, fp32 acc), split-K=2, fused mean-pool + z1-combined epilogue ──
__global__ void __launch_bounds__(NTHREADS, 1)
gemm_partial_kernel(const float* __restrict__ phrases, const float* __restrict__ bias,
                    float* __restrict__ out) {
    extern __shared__ char smem[];
    const uint32_t sb = smem_u32(smem);

    const int tid = threadIdx.x;
    const int warp = tid >> 5;      // 0..7
    const int lane = tid & 31;
    const int warp_m = warp & 1;    // 0..1 -> 64-row slab
    const int warp_n = warp >> 1;   // 0..3 -> 32-col slab
    const int m0 = blockIdx.y * BM;
    const int n0 = blockIdx.x * BN;
    const int kbase = blockIdx.z * KHALF;

    // pooling assignment: CTA linear id -> 8 phrase rows
    const int cid = blockIdx.z * (GN / BN) * (GM / BM) + blockIdx.y * (GN / BN) + blockIdx.x;
    const int prow0 = cid * PROWS;
    const float4* pf = (const float4*)(phrases + (size_t)prow0 * LL * DD) + tid;

    // cp.async mappings: tile = 128 rows x 8 16B-chunks (64 halves); 4 chunks/thread each
    uint32_t a_dst[4], b_dst[4];
    const __half* a_src[4];
    const __half* b_src[4];
#pragma unroll
    for (int i = 0; i < 4; i++) {
        int id = tid + i * NTHREADS;     // 0..1023
        int row = id >> 3, c8 = id & 7;
        a_dst[i] = row * (APH * 2) + c8 * 16;
        b_dst[i] = A_STAGE_BYTES + row * (APH * 2) + c8 * 16;
        a_src[i] = g_Ah + (size_t)(m0 + row) * GK + kbase + c8 * 8;
        b_src[i] = g_Wh + (size_t)(n0 + row) * GK + kbase + c8 * 8;
    }

    // ldmatrix lane bases (byte offsets within a stage)
    const int la_row = (lane & 7) + ((lane >> 3) & 1) * 8;
    const uint32_t pA_base = ((warp_m * 64 + la_row) * APH + (lane >> 4) * 8) * 2;
    const int lb_row = (lane & 7) + ((lane >> 4) & 1) * 8;
    const uint32_t pB_base =
        A_STAGE_BYTES + ((warp_n * 32 + lb_row) * APH + ((lane >> 3) & 1) * 8) * 2;

    float acc[4][4][4];
#pragma unroll
    for (int tm = 0; tm < 4; tm++)
#pragma unroll
        for (int tn = 0; tn < 4; tn++)
#pragma unroll
            for (int r = 0; r < 4; r++) acc[tm][tn][r] = 0.0f;

    // preload stages 0..STAGES-2
#pragma unroll
    for (int s = 0; s < STAGES - 1; s++) {
        const uint32_t st = sb + s * STAGE_BYTES;
        const int k0 = s * BK;
#pragma unroll
        for (int i = 0; i < 4; i++) {
            CP_ASYNC16(st + a_dst[i], a_src[i] + k0);
            CP_ASYNC16(st + b_dst[i], b_src[i] + k0);
        }
        CP_COMMIT();
    }

    // pool state: prefetch group 0 (steps 0..3)
    float4 pbuf[PGROUP];
#pragma unroll
    for (int j = 0; j < PGROUP; j++) pbuf[j] = __ldg(pf + j * (DD / 4));
    float pacc0 = 0.f, pacc1 = 0.f, pacc2 = 0.f, pacc3 = 0.f;
    float pinv = 0.f;
    int parow = 0, ppl = 0;

    uint32_t af[2][4][4], bf[2][4][2];

    for (int it = 0; it < NIT; it++) {
        CP_WAIT(STAGES - 2);
        __syncthreads();

        // issue loads for stage it+STAGES-1
        {
            const int ld = it + STAGES - 1;
            if (ld < NIT) {
                const uint32_t st = sb + (ld & (STAGES - 1)) * STAGE_BYTES;
                const int k0 = ld * BK;
#pragma unroll
                for (int i = 0; i < 4; i++) {
                    CP_ASYNC16(st + a_dst[i], a_src[i] + k0);
                    CP_ASYNC16(st + b_dst[i], b_src[i] + k0);
                }
            }
            CP_COMMIT();
        }

        // ── fused pooling: accumulate group `it` (already in pbuf), then prefetch it+1 ──
        if (it * PGROUP < PSTEPS) {
#pragma unroll
            for (int j = 0; j < PGROUP; j++) {
                if (ppl == 0) pinv = __ldg(g_invlen + prow0 + parow);
                pacc0 += pbuf[j].x; pacc1 += pbuf[j].y;
                pacc2 += pbuf[j].z; pacc3 += pbuf[j].w;
                ppl++;
                if (ppl == LL) {
                    float4 r = make_float4(pacc0 * pinv, pacc1 * pinv, pacc2 * pinv, pacc3 * pinv);
                    *((float4*)(out + (size_t)(prow0 + parow) * (2 * GN) + GN) + tid) = r;
                    pacc0 = pacc1 = pacc2 = pacc3 = 0.f;
                    ppl = 0;
                    parow++;
                }
            }
            const int sbase = (it + 1) * PGROUP;
            if (sbase < PSTEPS) {
#pragma unroll
                for (int j = 0; j < PGROUP; j++)
                    pbuf[j] = __ldg(pf + (sbase + j) * (DD / 4));
            }
        }

        const uint32_t st = sb + (it & (STAGES - 1)) * STAGE_BYTES;
        const uint32_t aA = st + pA_base;
        const uint32_t aB = st + pB_base;

        // prefetch fragments for ks=0
#pragma unroll
        for (int tm = 0; tm < 4; tm++)
            LDSM4(af[0][tm][0], af[0][tm][1], af[0][tm][2], af[0][tm][3],
                  aA + (tm * 16 * APH) * 2);
#pragma unroll
        for (int pr = 0; pr < 2; pr++)
            LDSM4(bf[0][pr * 2][0], bf[0][pr * 2][1], bf[0][pr * 2 + 1][0], bf[0][pr * 2 + 1][1],
                  aB + (pr * 16 * APH) * 2);

        // 4 k16-steps, register double-buffered
#pragma unroll
        for (int ks = 0; ks < 4; ks++) {
            const int cur = ks & 1, nxt = cur ^ 1;
            if (ks < 3) {
                const uint32_t ko = (ks + 1) * 32;  // 16 halves = 32 bytes
#pragma unroll
                for (int tm = 0; tm < 4; tm++)
                    LDSM4(af[nxt][tm][0], af[nxt][tm][1], af[nxt][tm][2], af[nxt][tm][3],
                          aA + (tm * 16 * APH) * 2 + ko);
#pragma unroll
                for (int pr = 0; pr < 2; pr++)
                    LDSM4(bf[nxt][pr * 2][0], bf[nxt][pr * 2][1],
                          bf[nxt][pr * 2 + 1][0], bf[nxt][pr * 2 + 1][1],
                          aB + (pr * 16 * APH) * 2 + ko);
            }
#pragma unroll
            for (int tm = 0; tm < 4; tm++)
#pragma unroll
                for (int tn = 0; tn < 4; tn++)
                    mma_f16(acc[tm][tn][0], acc[tm][tn][1], acc[tm][tn][2], acc[tm][tn][3],
                            af[cur][tm][0], af[cur][tm][1], af[cur][tm][2], af[cur][tm][3],
                            bf[cur][tn][0], bf[cur][tn][1]);
        }
    }

    const int tile = blockIdx.y * (GN / BN) + blockIdx.x;   // 0..199

    if (blockIdx.z == 0) {
        // producer: raw partial -> g_part, then publish flag
#pragma unroll
        for (int tn = 0; tn < 4; tn++) {
            const int n = n0 + warp_n * 32 + tn * 8 + (lane & 3) * 2;
#pragma unroll
            for (int tm = 0; tm < 4; tm++) {
                const int r0 = m0 + warp_m * 64 + tm * 16 + (lane >> 2);
                *(float2*)(g_part + (size_t)r0 * GN + n) =
                    make_float2(acc[tm][tn][0], acc[tm][tn][1]);
                *(float2*)(g_part + (size_t)(r0 + 8) * GN + n) =
                    make_float2(acc[tm][tn][2], acc[tm][tn][3]);
            }
        }
        __threadfence();
        __syncthreads();
        if (tid == 0) atomicExch(&g_flag[tile], 1);
    } else {
        // consumer: wait for partner (guaranteed earlier in bid order), combine
        if (tid == 0) {
            while (atomicAdd(&g_flag[tile], 0) == 0) { }
        }
        __syncthreads();
        __threadfence();
#pragma unroll
        for (int tn = 0; tn < 4; tn++) {
            const int n = n0 + warp_n * 32 + tn * 8 + (lane & 3) * 2;
            const float b0 = __ldg(bias + n);
            const float b1 = __ldg(bias + n + 1);
#pragma unroll
            for (int tm = 0; tm < 4; tm++) {
                const int r0 = m0 + warp_m * 64 + tm * 16 + (lane >> 2);
                float2 p0 = *(const float2*)(g_part + (size_t)r0 * GN + n);
                float2 p1 = *(const float2*)(g_part + (size_t)(r0 + 8) * GN + n);
                float2 v0, v1;
                v0.x = fmaxf(p0.x + acc[tm][tn][0] + b0, 0.0f);
                v0.y = fmaxf(p0.y + acc[tm][tn][1] + b1, 0.0f);
                v1.x = fmaxf(p1.x + acc[tm][tn][2] + b0, 0.0f);
                v1.y = fmaxf(p1.y + acc[tm][tn][3] + b1, 0.0f);
                *(float2*)(out + (size_t)r0 * (2 * GN) + n) = v0;
                *(float2*)(out + (size_t)(r0 + 8) * (2 * GN) + n) = v1;
            }
        }
        __syncthreads();
        if (tid == 0) g_flag[tile] = 0;   // reset for next launch / graph replay
    }
}

extern "C" void kernel_launch(void* const* d_in, const int* in_sizes, int n_in,
                              void* d_out, int out_size) {
    const float* features = (const float*)d_in[0];
    const float* phrases  = (const float*)d_in[1];
    const float* W        = (const float*)d_in[2];
    const float* bias     = (const float*)d_in[3];
    const int*   lens     = (const int*)d_in[4];
    float* out = (float*)d_out;

    cvt_f16_kernel<<<2048, 256>>>(features, W, lens);

    cudaFuncSetAttribute(gemm_partial_kernel, cudaFuncAttributeMaxDynamicSharedMemorySize,
                         SMEM_TOTAL);
    dim3 ggrid(GN / BN, GM / BM, KSPLIT);  // (8, 25, 2) = 400 CTAs, z-major bids
    gemm_partial_kernel<<<ggrid, NTHREADS, SMEM_TOTAL>>>(phrases, bias, out);
}

// round 17
// speedup vs baseline: 1.7659x; 1.0151x over previous
#include <cuda_runtime.h>
#include <cuda_fp16.h>
#include <cstdint>

// Problem dims
#define BB 64
#define RR 50
#define LL 15
#define DD 1024
#define FF 4096

// GEMM: M=B*R=3200, N=D=1024, K=F=4096
#define GM 3200
#define GN 1024
#define GK 4096

// CTA tile 128x128x64 (fp16), split-K=2 -> grid (8, 25, 2) = 400 CTAs.
#define BM 128
#define BN 128
#define BK 64
#define KSPLIT 2
#define KHALF (GK / KSPLIT)         // 2048
#define NIT (KHALF / BK)            // 32
#define APH 72                      // padded row stride in halves (144B, conflict-free)
#define STAGES 4
#define A_STAGE_BYTES (BM * APH * 2)          // 18432
#define STAGE_BYTES (2 * BM * APH * 2)        // 36864 (A + B)
#define SMEM_TOTAL (STAGES * STAGE_BYTES)     // 147456
#define NTHREADS 256

// pooling fused into GEMM: 400 CTAs x 8 rows, 120 row-steps, 4 per iteration
#define PROWS 8
#define PSTEPS (PROWS * LL)          // 120
#define PGROUP 4

// fp16(rna) copies of A and W; split partial scratch; 1/len
__device__ __half g_Ah[GM * GK];
__device__ __half g_Wh[GN * GK];
__device__ float g_part0[GM * GN];
__device__ float g_part1[GM * GN];
__device__ float g_invlen[GM];

__device__ __forceinline__ void mma_f16(float& c0, float& c1, float& c2, float& c3,
                                        uint32_t a0, uint32_t a1, uint32_t a2, uint32_t a3,
                                        uint32_t b0, uint32_t b1) {
    asm volatile(
        "mma.sync.aligned.m16n8k16.row.col.f32.f16.f16.f32 "
        "{%0,%1,%2,%3}, {%4,%5,%6,%7}, {%8,%9}, {%0,%1,%2,%3};\n"
        : "+f"(c0), "+f"(c1), "+f"(c2), "+f"(c3)
        : "r"(a0), "r"(a1), "r"(a2), "r"(a3), "r"(b0), "r"(b1));
}

__device__ __forceinline__ uint32_t smem_u32(const void* p) {
    uint32_t a;
    asm("{ .reg .u64 t; cvta.to.shared.u64 t, %1; cvt.u32.u64 %0, t; }" : "=r"(a) : "l"(p));
    return a;
}

#define CP_ASYNC16(dst, src) \
    asm volatile("cp.async.cg.shared.global [%0], [%1], 16;" :: "r"(dst), "l"(src) : "memory")
#define CP_COMMIT() asm volatile("cp.async.commit_group;" ::: "memory")
#define CP_WAIT(n) asm volatile("cp.async.wait_group %0;" :: "n"(n) : "memory")

#define LDSM4(r0, r1, r2, r3, addr) \
    asm volatile("ldmatrix.sync.aligned.m8n8.x4.shared.b16 {%0,%1,%2,%3}, [%4];" \
                 : "=r"(r0), "=r"(r1), "=r"(r2), "=r"(r3) : "r"(addr))

__device__ __forceinline__ uint4 cvt8(const float4* src) {
    float4 v0 = __ldg(src);
    float4 v1 = __ldg(src + 1);
    __half2 h0 = __floats2half2_rn(v0.x, v0.y);
    __half2 h1 = __floats2half2_rn(v0.z, v0.w);
    __half2 h2 = __floats2half2_rn(v1.x, v1.y);
    __half2 h3 = __floats2half2_rn(v1.z, v1.w);
    uint4 o;
    o.x = *(uint32_t*)&h0;
    o.y = *(uint32_t*)&h1;
    o.z = *(uint32_t*)&h2;
    o.w = *(uint32_t*)&h3;
    return o;
}

// ─────────────────── prepass: fp32 -> fp16(rna), plus 1/len ───────────────────
// branch-free phases: one grid-stride loop for A, one for W
__global__ void __launch_bounds__(256)
cvt_f16_kernel(const float* __restrict__ A, const float* __restrict__ W,
               const int* __restrict__ lens) {
    const int gid = blockIdx.x * blockDim.x + threadIdx.x;
    const int gstride = gridDim.x * blockDim.x;
    if (gid < GM) g_invlen[gid] = 1.0f / (float)__ldg(lens + gid);

    const int na8 = GM * GK / 8;   // 16B output chunks for A
    const int nw8 = GN * GK / 8;
#pragma unroll 2
    for (int i = gid; i < na8; i += gstride)
        *((uint4*)g_Ah + i) = cvt8((const float4*)A + (size_t)i * 2);
#pragma unroll 2
    for (int i = gid; i < nw8; i += gstride)
        *((uint4*)g_Wh + i) = cvt8((const float4*)W + (size_t)i * 2);
}

// ── GEMM partials (fp16 in, fp32 acc), split-K=2, fused mean-pool (= R7 body) ──
__global__ void __launch_bounds__(NTHREADS, 1)
gemm_partial_kernel(const float* __restrict__ phrases, float* __restrict__ out) {
    extern __shared__ char smem[];
    const uint32_t sb = smem_u32(smem);

    const int tid = threadIdx.x;
    const int warp = tid >> 5;      // 0..7
    const int lane = tid & 31;
    const int warp_m = warp & 1;    // 0..1 -> 64-row slab
    const int warp_n = warp >> 1;   // 0..3 -> 32-col slab
    const int m0 = blockIdx.y * BM;
    const int n0 = blockIdx.x * BN;
    const int kbase = blockIdx.z * KHALF;

    // pooling assignment: CTA linear id -> 8 phrase rows
    const int cid = blockIdx.z * (GN / BN) * (GM / BM) + blockIdx.y * (GN / BN) + blockIdx.x;
    const int prow0 = cid * PROWS;
    const float4* pf = (const float4*)(phrases + (size_t)prow0 * LL * DD) + tid;

    // cp.async mappings: tile = 128 rows x 8 16B-chunks (64 halves); 4 chunks/thread each
    uint32_t a_dst[4], b_dst[4];
    const __half* a_src[4];
    const __half* b_src[4];
#pragma unroll
    for (int i = 0; i < 4; i++) {
        int id = tid + i * NTHREADS;     // 0..1023
        int row = id >> 3, c8 = id & 7;
        a_dst[i] = row * (APH * 2) + c8 * 16;
        b_dst[i] = A_STAGE_BYTES + row * (APH * 2) + c8 * 16;
        a_src[i] = g_Ah + (size_t)(m0 + row) * GK + kbase + c8 * 8;
        b_src[i] = g_Wh + (size_t)(n0 + row) * GK + kbase + c8 * 8;
    }

    // ldmatrix lane bases (byte offsets within a stage)
    const int la_row = (lane & 7) + ((lane >> 3) & 1) * 8;
    const uint32_t pA_base = ((warp_m * 64 + la_row) * APH + (lane >> 4) * 8) * 2;
    const int lb_row = (lane & 7) + ((lane >> 4) & 1) * 8;
    const uint32_t pB_base =
        A_STAGE_BYTES + ((warp_n * 32 + lb_row) * APH + ((lane >> 3) & 1) * 8) * 2;

    float acc[4][4][4];
#pragma unroll
    for (int tm = 0; tm < 4; tm++)
#pragma unroll
        for (int tn = 0; tn < 4; tn++)
#pragma unroll
            for (int r = 0; r < 4; r++) acc[tm][tn][r] = 0.0f;

    // preload stages 0..STAGES-2
#pragma unroll
    for (int s = 0; s < STAGES - 1; s++) {
        const uint32_t st = sb + s * STAGE_BYTES;
        const int k0 = s * BK;
#pragma unroll
        for (int i = 0; i < 4; i++) {
            CP_ASYNC16(st + a_dst[i], a_src[i] + k0);
            CP_ASYNC16(st + b_dst[i], b_src[i] + k0);
        }
        CP_COMMIT();
    }

    // pool state: prefetch group 0 (steps 0..3)
    float4 pbuf[PGROUP];
#pragma unroll
    for (int j = 0; j < PGROUP; j++) pbuf[j] = __ldg(pf + j * (DD / 4));
    float pacc0 = 0.f, pacc1 = 0.f, pacc2 = 0.f, pacc3 = 0.f;
    float pinv = 0.f;
    int parow = 0, ppl = 0;

    uint32_t af[2][4][4], bf[2][4][2];

    for (int it = 0; it < NIT; it++) {
        CP_WAIT(STAGES - 2);
        __syncthreads();

        // issue loads for stage it+STAGES-1
        {
            const int ld = it + STAGES - 1;
            if (ld < NIT) {
                const uint32_t st = sb + (ld & (STAGES - 1)) * STAGE_BYTES;
                const int k0 = ld * BK;
#pragma unroll
                for (int i = 0; i < 4; i++) {
                    CP_ASYNC16(st + a_dst[i], a_src[i] + k0);
                    CP_ASYNC16(st + b_dst[i], b_src[i] + k0);
                }
            }
            CP_COMMIT();
        }

        // ── fused pooling: accumulate group `it` (already in pbuf), then prefetch it+1 ──
        if (it * PGROUP < PSTEPS) {
#pragma unroll
            for (int j = 0; j < PGROUP; j++) {
                if (ppl == 0) pinv = __ldg(g_invlen + prow0 + parow);
                pacc0 += pbuf[j].x; pacc1 += pbuf[j].y;
                pacc2 += pbuf[j].z; pacc3 += pbuf[j].w;
                ppl++;
                if (ppl == LL) {
                    float4 r = make_float4(pacc0 * pinv, pacc1 * pinv, pacc2 * pinv, pacc3 * pinv);
                    *((float4*)(out + (size_t)(prow0 + parow) * (2 * GN) + GN) + tid) = r;
                    pacc0 = pacc1 = pacc2 = pacc3 = 0.f;
                    ppl = 0;
                    parow++;
                }
            }
            const int sbase = (it + 1) * PGROUP;
            if (sbase < PSTEPS) {
#pragma unroll
                for (int j = 0; j < PGROUP; j++)
                    pbuf[j] = __ldg(pf + (sbase + j) * (DD / 4));
            }
        }

        const uint32_t st = sb + (it & (STAGES - 1)) * STAGE_BYTES;
        const uint32_t aA = st + pA_base;
        const uint32_t aB = st + pB_base;

        // prefetch fragments for ks=0
#pragma unroll
        for (int tm = 0; tm < 4; tm++)
            LDSM4(af[0][tm][0], af[0][tm][1], af[0][tm][2], af[0][tm][3],
                  aA + (tm * 16 * APH) * 2);
#pragma unroll
        for (int pr = 0; pr < 2; pr++)
            LDSM4(bf[0][pr * 2][0], bf[0][pr * 2][1], bf[0][pr * 2 + 1][0], bf[0][pr * 2 + 1][1],
                  aB + (pr * 16 * APH) * 2);

        // 4 k16-steps, register double-buffered
#pragma unroll
        for (int ks = 0; ks < 4; ks++) {
            const int cur = ks & 1, nxt = cur ^ 1;
            if (ks < 3) {
                const uint32_t ko = (ks + 1) * 32;  // 16 halves = 32 bytes
#pragma unroll
                for (int tm = 0; tm < 4; tm++)
                    LDSM4(af[nxt][tm][0], af[nxt][tm][1], af[nxt][tm][2], af[nxt][tm][3],
                          aA + (tm * 16 * APH) * 2 + ko);
#pragma unroll
                for (int pr = 0; pr < 2; pr++)
                    LDSM4(bf[nxt][pr * 2][0], bf[nxt][pr * 2][1],
                          bf[nxt][pr * 2 + 1][0], bf[nxt][pr * 2 + 1][1],
                          aB + (pr * 16 * APH) * 2 + ko);
            }
#pragma unroll
            for (int tm = 0; tm < 4; tm++)
#pragma unroll
                for (int tn = 0; tn < 4; tn++)
                    mma_f16(acc[tm][tn][0], acc[tm][tn][1], acc[tm][tn][2], acc[tm][tn][3],
                            af[cur][tm][0], af[cur][tm][1], af[cur][tm][2], af[cur][tm][3],
                            bf[cur][tn][0], bf[cur][tn][1]);
        }
    }

    // write raw partial to split scratch
    float* pdst = (blockIdx.z == 0) ? g_part0 : g_part1;
#pragma unroll
    for (int tn = 0; tn < 4; tn++) {
        const int n = n0 + warp_n * 32 + tn * 8 + (lane & 3) * 2;
#pragma unroll
        for (int tm = 0; tm < 4; tm++) {
            const int r0 = m0 + warp_m * 64 + tm * 16 + (lane >> 2);
            *(float2*)(pdst + (size_t)r0 * GN + n) = make_float2(acc[tm][tn][0], acc[tm][tn][1]);
            *(float2*)(pdst + (size_t)(r0 + 8) * GN + n) = make_float2(acc[tm][tn][2], acc[tm][tn][3]);
        }
    }
}

// ─────────────── reduce: out[:,0:1024] = relu(p0 + p1 + bias) ───────────────
// 800 blocks x 256 threads x 4 float4 each (grid-constant mapping, L2-resident partials)
__global__ void __launch_bounds__(256)
reduce_kernel(const float* __restrict__ bias, float* __restrict__ out) {
    const int base = (blockIdx.x * 256 + threadIdx.x) * 4;   // float4 index, 0..819199 step
#pragma unroll
    for (int j = 0; j < 4; j++) {
        const int idx = base + j;                 // global float4 id in [3200*256]
        const int row = idx >> 8;                 // /256 float4s per row
        const int c4 = idx & 255;
        float4 p0 = __ldg((const float4*)(g_part0 + (size_t)row * GN) + c4);
        float4 p1 = __ldg((const float4*)(g_part1 + (size_t)row * GN) + c4);
        float4 bv = __ldg((const float4*)bias + c4);
        float4 v;
        v.x = fmaxf(p0.x + p1.x + bv.x, 0.0f);
        v.y = fmaxf(p0.y + p1.y + bv.y, 0.0f);
        v.z = fmaxf(p0.z + p1.z + bv.z, 0.0f);
        v.w = fmaxf(p0.w + p1.w + bv.w, 0.0f);
        *((float4*)(out + (size_t)row * (2 * GN)) + c4) = v;
    }
}

extern "C" void kernel_launch(void* const* d_in, const int* in_sizes, int n_in,
                              void* d_out, int out_size) {
    const float* features = (const float*)d_in[0];
    const float* phrases  = (const float*)d_in[1];
    const float* W        = (const float*)d_in[2];
    const float* bias     = (const float*)d_in[3];
    const int*   lens     = (const int*)d_in[4];
    float* out = (float*)d_out;

    cvt_f16_kernel<<<2048, 256>>>(features, W, lens);

    cudaFuncSetAttribute(gemm_partial_kernel, cudaFuncAttributeMaxDynamicSharedMemorySize,
                         SMEM_TOTAL);
    dim3 ggrid(GN / BN, GM / BM, KSPLIT);  // (8, 25, 2) = 400 CTAs
    gemm_partial_kernel<<<ggrid, NTHREADS, SMEM_TOTAL>>>(phrases, out);

    reduce_kernel<<<800, 256>>>(bias, out);
}